// round 10
// baseline (speedup 1.0000x reference)
#include <cuda_runtime.h>
#include <math.h>

#define H 1024
#define V 50257
#define S 4096
#define NT 256
#define NCHAIN 256      // co-resident (2/SM x >=128 SMs); barriers count these

// ---------------- scratch (__device__ globals) ----------------
__device__ float g_gi[3 * H];
__device__ float g_gh[3 * H];
__device__ float g_h[H];
__device__ float g_vpart[16][H];     // 16 j-chunks of 64 rows
__device__ float g_scores[S];
__device__ float g_ctxpart[64][H];   // 64 s-chunks of 64 rows
__device__ float g_ctx[H];
__device__ unsigned g_cnt = 0;
__device__ unsigned g_gen = 0;
__device__ unsigned g_cnt2 = 0;      // last-arriver counter for ctx reduce

// ---------------- helpers ----------------
__device__ __forceinline__ float warp_sum(float v) {
#pragma unroll
    for (int o = 16; o; o >>= 1) v += __shfl_xor_sync(0xffffffffu, v, o);
    return v;
}

__device__ __forceinline__ void chain_sync() {
    __syncthreads();
    if (threadIdx.x == 0) {
        __threadfence();
        unsigned gen = *(volatile unsigned*)&g_gen;
        if (atomicAdd(&g_cnt, 1u) == NCHAIN - 1) {
            g_cnt = 0;
            __threadfence();
            *(volatile unsigned*)&g_gen = gen + 1;
        } else {
            while (*(volatile unsigned*)&g_gen == gen) { }
        }
        __threadfence();
    }
    __syncthreads();
}

// ---------------- kernel 1: chain, 3 grid barriers + last-arriver reduce ------
__global__ void __launch_bounds__(NT, 2)
k_chain(const int* __restrict__ word,
        const float* __restrict__ last_hidden,
        const float* __restrict__ enc,
        const float* __restrict__ emb,
        const float* __restrict__ w_ih,
        const float* __restrict__ w_hh,
        const float* __restrict__ b_ih,
        const float* __restrict__ b_hh,
        const float* __restrict__ attn_w,
        float* __restrict__ dout) {
    __shared__ float4 sbuf4[512];     // [0..255]: x then h ; [256..511]: h_prev then v
    __shared__ float red[64];
    __shared__ float bc;
    __shared__ float w_sh[64];
    __shared__ int lastf;
    float* h_sh = (float*)sbuf4;                 // after GRU (blocks < 64)
    float4* v_sh4 = sbuf4 + 256;                 // after local vred

    const int t = threadIdx.x;
    const int b = blockIdx.x;
    const int warp = t >> 5, lane = t & 31;
    const int nwarp = NCHAIN * (NT / 32);        // 2048
    const int gw = b * (NT / 32) + warp;

    // ===== Phase 1: gates — 3 rows per warp, loads interleaved for MLP
    {
        const float* x = emb + (long)word[0] * H;
        sbuf4[t]       = reinterpret_cast<const float4*>(x)[t];
        sbuf4[256 + t] = reinterpret_cast<const float4*>(last_hidden)[t];
        __syncthreads();

        const float4* p[3];
        const float4* vv[3];
        float bias[3];
        float* outp[3];
#pragma unroll
        for (int k = 0; k < 3; k++) {
            int r = gw + k * nwarp;              // exact: 6144 = 3*2048
            if (r < 3 * H) {
                p[k] = reinterpret_cast<const float4*>(w_ih + (long)r * H);
                vv[k] = sbuf4; bias[k] = b_ih[r]; outp[k] = &g_gi[r];
            } else {
                int rr = r - 3 * H;
                p[k] = reinterpret_cast<const float4*>(w_hh + (long)rr * H);
                vv[k] = sbuf4 + 256; bias[k] = b_hh[rr]; outp[k] = &g_gh[rr];
            }
        }
        float a0 = 0.f, a1 = 0.f, a2 = 0.f;
#pragma unroll
        for (int it = 0; it < 8; it++) {
            float4 w0 = p[0][it * 32 + lane];
            float4 w1 = p[1][it * 32 + lane];
            float4 w2 = p[2][it * 32 + lane];
            float4 c0 = vv[0][it * 32 + lane];
            float4 c1 = vv[1][it * 32 + lane];
            float4 c2 = vv[2][it * 32 + lane];
            a0 += w0.x * c0.x + w0.y * c0.y + w0.z * c0.z + w0.w * c0.w;
            a1 += w1.x * c1.x + w1.y * c1.y + w1.z * c1.z + w1.w * c1.w;
            a2 += w2.x * c2.x + w2.y * c2.y + w2.z * c2.z + w2.w * c2.w;
        }
        a0 = warp_sum(a0); a1 = warp_sum(a1); a2 = warp_sum(a2);
        if (!lane) { *outp[0] = a0 + bias[0]; *outp[1] = a1 + bias[1]; *outp[2] = a2 + bias[2]; }
    }
    chain_sync();   // barrier 1

    // ===== Phase 2 (blocks 0..63): local GRU -> h_sh, then v partials
    if (b < 64) {
#pragma unroll
        for (int k = 0; k < 4; k++) {
            int i = t + NT * k;
            float hp = ((const float*)(sbuf4 + 256))[i];   // h_prev still in shared
            float r = 1.f / (1.f + expf(-(g_gi[i] + g_gh[i])));
            float z = 1.f / (1.f + expf(-(g_gi[H + i] + g_gh[H + i])));
            float n = tanhf(g_gi[2 * H + i] + r * g_gh[2 * H + i]);
            float h = (1.f - z) * n + z * hp;
            h_sh[i] = h;                                    // overwrites x (done)
            if (b == 0) { g_h[i] = h; dout[V + i] = h; }    // hidden output + publish
        }
        __syncthreads();

        int jc = b >> 2;                                    // 16 chunks of 64 rows
        int c = (b & 3) * NT + t;
        const float* base = attn_w + (long)(jc * 64) * H + c;
        float s = 0.f;
#pragma unroll 8
        for (int j = 0; j < 64; j++)
            s += base[(long)j * H] * h_sh[jc * 64 + j];
        g_vpart[jc][c] = s;
    }
    chain_sync();   // barrier 2

    // ===== Phase 3a: local vred (all blocks): v -> shared
    {
        float4 acc = make_float4(0.f, 0.f, 0.f, 0.f);
#pragma unroll
        for (int j = 0; j < 16; j++) {
            float4 pv = reinterpret_cast<const float4*>(g_vpart[j])[t];
            acc.x += pv.x; acc.y += pv.y; acc.z += pv.z; acc.w += pv.w;
        }
        v_sh4[t] = acc;                                     // overwrites h_prev slot
        __syncthreads();
    }

    // ===== Phase 3b: scores — 2 rows per warp, interleaved (attn_b invariant)
    {
        const float4* e0 = reinterpret_cast<const float4*>(enc + (long)gw * H);
        const float4* e1 = reinterpret_cast<const float4*>(enc + (long)(gw + nwarp) * H);
        float a0 = 0.f, a1 = 0.f;
#pragma unroll
        for (int it = 0; it < 8; it++) {
            float4 x0 = e0[it * 32 + lane];
            float4 x1 = e1[it * 32 + lane];
            float4 vv = v_sh4[it * 32 + lane];
            a0 += x0.x * vv.x + x0.y * vv.y + x0.z * vv.z + x0.w * vv.w;
            a1 += x1.x * vv.x + x1.y * vv.y + x1.z * vv.z + x1.w * vv.w;
        }
        a0 = warp_sum(a0); a1 = warp_sum(a1);
        if (!lane) { g_scores[gw] = a0; g_scores[gw + nwarp] = a1; }
    }
    chain_sync();   // barrier 3

    // ===== Phase 4a: local softmax normalization (all blocks)
    float e_loc[16];
    {
        float x[16];
        float m = -INFINITY;
#pragma unroll
        for (int k = 0; k < 16; k++) {
            x[k] = g_scores[t + NT * k];
            m = fmaxf(m, x[k]);
        }
#pragma unroll
        for (int o = 16; o; o >>= 1) m = fmaxf(m, __shfl_xor_sync(0xffffffffu, m, o));
        if (!lane) red[warp] = m;
        __syncthreads();
        if (warp == 0) {
            m = (lane < 8) ? red[lane] : -INFINITY;
#pragma unroll
            for (int o = 4; o; o >>= 1) m = fmaxf(m, __shfl_xor_sync(0xffffffffu, m, o));
            if (!lane) bc = m;
        }
        __syncthreads();
        m = bc;
        float sum = 0.f;
#pragma unroll
        for (int k = 0; k < 16; k++) { e_loc[k] = expf(x[k] - m); sum += e_loc[k]; }
        sum = warp_sum(sum);
        __syncthreads();
        if (!lane) red[warp] = sum;
        __syncthreads();
        if (warp == 0) {
            sum = (lane < 8) ? red[lane] : 0.f;
#pragma unroll
            for (int o = 4; o; o >>= 1) sum += __shfl_xor_sync(0xffffffffu, sum, o);
            if (!lane) bc = sum;
        }
        __syncthreads();
    }
    const float inv = 1.f / bc;

    // block 0 writes attn_weights output
    if (b == 0) {
#pragma unroll
        for (int k = 0; k < 16; k++)
            dout[V + H + t + NT * k] = e_loc[k] * inv;
    }

    // ===== Phase 4b: ctx partials (all 256 blocks): 64 chunks x 4 col-groups
    {
        const int sc = b >> 2;                    // rows [sc*64, sc*64+64)
        const int c = (b & 3) * NT + t;
        // scatter this block's chunk weights into shared via e_loc coverage
#pragma unroll
        for (int k = 0; k < 16; k++) {
            int s = t + NT * k;
            int j = s - sc * 64;
            if (j >= 0 && j < 64) w_sh[j] = e_loc[k] * inv;
        }
        __syncthreads();

        const float* base = enc + (long)(sc * 64) * H + c;
        float acc = 0.f;
#pragma unroll 8
        for (int s = 0; s < 64; s++)
            acc += w_sh[s] * base[(long)s * H];
        g_ctxpart[sc][c] = acc;
    }

    // ===== Phase 5: last-arriver does the ctx reduce; everyone else exits
    __threadfence();
    __syncthreads();
    if (t == 0) lastf = (atomicAdd(&g_cnt2, 1u) == NCHAIN - 1) ? 1 : 0;
    __syncthreads();
    if (lastf) {
        __threadfence();                          // acquire others' partials
        float4 acc = make_float4(0.f, 0.f, 0.f, 0.f);
#pragma unroll
        for (int j = 0; j < 64; j++) {
            float4 pv = reinterpret_cast<const float4*>(g_ctxpart[j])[t];
            acc.x += pv.x; acc.y += pv.y; acc.z += pv.z; acc.w += pv.w;
        }
        reinterpret_cast<float4*>(g_ctx)[t] = acc;
        if (t == 0) g_cnt2 = 0;                   // reset for next replay
    }
}

// ---------------- kernel 2: logits (flat; measured 6.62 TB/s — FROZEN) --------
__global__ void k_logits(const float* __restrict__ out_w,
                         const float* __restrict__ out_b,
                         float* __restrict__ dout) {
    __shared__ float4 cat[512];  // [h | ctx]
    int t = threadIdx.x;
    cat[t] = reinterpret_cast<const float4*>(g_h)[t];
    cat[256 + t] = reinterpret_cast<const float4*>(g_ctx)[t];
    __syncthreads();

    int warp = t >> 5, lane = t & 31;
    int r = blockIdx.x * 8 + warp;
    if (r >= V) return;
    const float4* wr = reinterpret_cast<const float4*>(out_w + (long)r * (2 * H));
    float acc = 0.f;
#pragma unroll
    for (int it = 0; it < 16; it++) {
        float4 w = wr[it * 32 + lane];
        float4 c = cat[it * 32 + lane];
        acc += w.x * c.x + w.y * c.y + w.z * c.z + w.w * c.w;
    }
    acc = warp_sum(acc);
    if (!lane) dout[r] = acc + out_b[r];
}

// ---------------- launch ----------------
extern "C" void kernel_launch(void* const* d_in, const int* in_sizes, int n_in,
                              void* d_out, int out_size) {
    const int* word = (const int*)d_in[0];
    const float* last_hidden = (const float*)d_in[1];
    const float* enc = (const float*)d_in[2];
    const float* emb = (const float*)d_in[3];
    const float* w_ih = (const float*)d_in[4];
    const float* w_hh = (const float*)d_in[5];
    const float* b_ih = (const float*)d_in[6];
    const float* b_hh = (const float*)d_in[7];
    const float* attn_w = (const float*)d_in[8];
    // d_in[9] = attn_b : constant pre-softmax shift -> softmax-invariant, dropped
    const float* out_w = (const float*)d_in[10];
    const float* out_b = (const float*)d_in[11];
    float* dout = (float*)d_out;

    k_chain<<<NCHAIN, NT>>>(word, last_hidden, enc, emb, w_ih, w_hh, b_ih, b_hh,
                            attn_w, dout);
    k_logits<<<(V + 7) / 8, 256>>>(out_w, out_b, dout);
}

// round 11
// speedup vs baseline: 1.0030x; 1.0030x over previous
#include <cuda_runtime.h>
#include <math.h>

#define H 1024
#define V 50257
#define S 4096
#define NT 256
#define NCHAIN 256      // co-resident blocks for the gates barrier

// ---------------- scratch (__device__ globals) ----------------
__device__ float g_gi[3 * H];
__device__ float g_gh[3 * H];
__device__ float g_h[H];
__device__ float g_vpart[16][H];     // 16 j-chunks of 64 rows
__device__ float g_scores[S];
__device__ float g_ctxpart[64][H];   // 64 s-chunks of 64 rows
__device__ float g_ctx[H];
__device__ float g_logh[V];
__device__ unsigned g_cnt = 0;
__device__ unsigned g_gen = 0;

// ---------------- helpers ----------------
__device__ __forceinline__ float warp_sum(float v) {
#pragma unroll
    for (int o = 16; o; o >>= 1) v += __shfl_xor_sync(0xffffffffu, v, o);
    return v;
}

__device__ __forceinline__ void chain_sync() {
    __syncthreads();
    if (threadIdx.x == 0) {
        __threadfence();
        unsigned gen = *(volatile unsigned*)&g_gen;
        if (atomicAdd(&g_cnt, 1u) == NCHAIN - 1) {
            g_cnt = 0;
            __threadfence();
            *(volatile unsigned*)&g_gen = gen + 1;
        } else {
            while (*(volatile unsigned*)&g_gen == gen) { }
        }
        __threadfence();
    }
    __syncthreads();
}

__device__ __forceinline__ float warp_dot(const float4* __restrict__ p,
                                          const float4* vec, int lane) {
    float acc = 0.f;
#pragma unroll
    for (int it = 0; it < 8; it++) {
        float4 w = p[it * 32 + lane];
        float4 c = vec[it * 32 + lane];
        acc += w.x * c.x + w.y * c.y + w.z * c.z + w.w * c.w;
    }
    return warp_sum(acc);
}

// ================= K1: gates + GRU (persistent, 1 barrier) =================
__global__ void __launch_bounds__(NT, 2)
k_gates_gru(const int* __restrict__ word,
            const float* __restrict__ last_hidden,
            const float* __restrict__ emb,
            const float* __restrict__ w_ih,
            const float* __restrict__ w_hh,
            const float* __restrict__ b_ih,
            const float* __restrict__ b_hh,
            float* __restrict__ dout) {
    __shared__ float4 sbuf4[512];   // [0..255]: x ; [256..511]: h_prev
    const int t = threadIdx.x;
    const int b = blockIdx.x;
    const int warp = t >> 5, lane = t & 31;
    const int nwarp = NCHAIN * (NT / 32);        // 2048
    const int gw = b * (NT / 32) + warp;

    {
        const float* x = emb + (long)word[0] * H;
        sbuf4[t]       = reinterpret_cast<const float4*>(x)[t];
        sbuf4[256 + t] = reinterpret_cast<const float4*>(last_hidden)[t];
        __syncthreads();

        const float4* p[3];
        const float4* vv[3];
        float bias[3];
        float* outp[3];
#pragma unroll
        for (int k = 0; k < 3; k++) {
            int r = gw + k * nwarp;              // 6144 = 3 * 2048 exact
            if (r < 3 * H) {
                p[k] = reinterpret_cast<const float4*>(w_ih + (long)r * H);
                vv[k] = sbuf4; bias[k] = b_ih[r]; outp[k] = &g_gi[r];
            } else {
                int rr = r - 3 * H;
                p[k] = reinterpret_cast<const float4*>(w_hh + (long)rr * H);
                vv[k] = sbuf4 + 256; bias[k] = b_hh[rr]; outp[k] = &g_gh[rr];
            }
        }
        float a0 = 0.f, a1 = 0.f, a2 = 0.f;
#pragma unroll
        for (int it = 0; it < 8; it++) {
            float4 w0 = p[0][it * 32 + lane];
            float4 w1 = p[1][it * 32 + lane];
            float4 w2 = p[2][it * 32 + lane];
            float4 c0 = vv[0][it * 32 + lane];
            float4 c1 = vv[1][it * 32 + lane];
            float4 c2 = vv[2][it * 32 + lane];
            a0 += w0.x * c0.x + w0.y * c0.y + w0.z * c0.z + w0.w * c0.w;
            a1 += w1.x * c1.x + w1.y * c1.y + w1.z * c1.z + w1.w * c1.w;
            a2 += w2.x * c2.x + w2.y * c2.y + w2.z * c2.z + w2.w * c2.w;
        }
        a0 = warp_sum(a0); a1 = warp_sum(a1); a2 = warp_sum(a2);
        if (!lane) { *outp[0] = a0 + bias[0]; *outp[1] = a1 + bias[1]; *outp[2] = a2 + bias[2]; }
    }
    chain_sync();

    // GRU: blocks 0..3 publish h (h_prev still in shared)
    if (b < 4) {
        int i = b * NT + t;
        float hp = ((const float*)(sbuf4 + 256))[i];
        float r = 1.f / (1.f + expf(-(g_gi[i] + g_gh[i])));
        float z = 1.f / (1.f + expf(-(g_gi[H + i] + g_gh[H + i])));
        float n = tanhf(g_gi[2 * H + i] + r * g_gh[2 * H + i]);
        float h = (1.f - z) * n + z * hp;
        g_h[i] = h;
        dout[V + i] = h;                 // hidden output
    }
}

// ================= branch A (no barriers) =================
// A1: v partials  v[c] = sum_j attn_w[j][c] * h[j]
__global__ void k_vpart(const float* __restrict__ attn_w) {
    __shared__ float h_sh[H];
    int t = threadIdx.x, b = blockIdx.x;
#pragma unroll
    for (int k = 0; k < 4; k++) h_sh[t + NT * k] = g_h[t + NT * k];
    __syncthreads();
    int jc = b >> 2;
    int c = (b & 3) * NT + t;
    const float* base = attn_w + (long)(jc * 64) * H + c;
    float s = 0.f;
#pragma unroll 8
    for (int j = 0; j < 64; j++)
        s += base[(long)j * H] * h_sh[jc * 64 + j];
    g_vpart[jc][c] = s;
}

// A2: local vred + scores (512 blocks x 8 scores)
__global__ void k_scores(const float* __restrict__ enc) {
    __shared__ float4 v_sh4[256];
    int t = threadIdx.x, b = blockIdx.x;
    int warp = t >> 5, lane = t & 31;
    float4 acc = make_float4(0.f, 0.f, 0.f, 0.f);
#pragma unroll
    for (int j = 0; j < 16; j++) {
        float4 pv = reinterpret_cast<const float4*>(g_vpart[j])[t];
        acc.x += pv.x; acc.y += pv.y; acc.z += pv.z; acc.w += pv.w;
    }
    v_sh4[t] = acc;
    __syncthreads();
    int s = b * 8 + warp;
    float a = warp_dot(reinterpret_cast<const float4*>(enc + (long)s * H), v_sh4, lane);
    if (!lane) g_scores[s] = a;
}

// A3: local softmax + ctx partials (256 blocks; attn_b softmax-invariant)
__global__ void k_softctx(const float* __restrict__ enc, float* __restrict__ dout) {
    __shared__ float red[64];
    __shared__ float bc;
    __shared__ float w_sh[64];
    int t = threadIdx.x, b = blockIdx.x;
    int warp = t >> 5, lane = t & 31;

    float e_loc[16];
    {
        float x[16];
        float m = -INFINITY;
#pragma unroll
        for (int k = 0; k < 16; k++) {
            x[k] = g_scores[t + NT * k];
            m = fmaxf(m, x[k]);
        }
#pragma unroll
        for (int o = 16; o; o >>= 1) m = fmaxf(m, __shfl_xor_sync(0xffffffffu, m, o));
        if (!lane) red[warp] = m;
        __syncthreads();
        if (warp == 0) {
            m = (lane < 8) ? red[lane] : -INFINITY;
#pragma unroll
            for (int o = 4; o; o >>= 1) m = fmaxf(m, __shfl_xor_sync(0xffffffffu, m, o));
            if (!lane) bc = m;
        }
        __syncthreads();
        m = bc;
        float sum = 0.f;
#pragma unroll
        for (int k = 0; k < 16; k++) { e_loc[k] = expf(x[k] - m); sum += e_loc[k]; }
        sum = warp_sum(sum);
        __syncthreads();
        if (!lane) red[warp] = sum;
        __syncthreads();
        if (warp == 0) {
            sum = (lane < 8) ? red[lane] : 0.f;
#pragma unroll
            for (int o = 4; o; o >>= 1) sum += __shfl_xor_sync(0xffffffffu, sum, o);
            if (!lane) bc = sum;
        }
        __syncthreads();
    }
    const float inv = 1.f / bc;

    if (b == 0) {
#pragma unroll
        for (int k = 0; k < 16; k++)
            dout[V + H + t + NT * k] = e_loc[k] * inv;   // attn_weights output
    }

    const int sc = b >> 2;                    // rows [sc*64, sc*64+64)
    const int c = (b & 3) * NT + t;
#pragma unroll
    for (int k = 0; k < 16; k++) {
        int s = t + NT * k;
        int j = s - sc * 64;
        if (j >= 0 && j < 64) w_sh[j] = e_loc[k] * inv;
    }
    __syncthreads();

    const float* base = enc + (long)(sc * 64) * H + c;
    float acc = 0.f;
#pragma unroll 8
    for (int s = 0; s < 64; s++)
        acc += w_sh[s] * base[(long)s * H];
    g_ctxpart[sc][c] = acc;
}

// A4: ctx reduce (1 block, float4)
__global__ void k_ctxred() {
    int t = threadIdx.x;
    float4 acc = make_float4(0.f, 0.f, 0.f, 0.f);
#pragma unroll
    for (int j = 0; j < 64; j++) {
        float4 pv = reinterpret_cast<const float4*>(g_ctxpart[j])[t];
        acc.x += pv.x; acc.y += pv.y; acc.z += pv.z; acc.w += pv.w;
    }
    reinterpret_cast<float4*>(g_ctx)[t] = acc;
}

// ================= branch B: logits h-half (flat, 206MB stream) =================
__global__ void k_logits_h(const float* __restrict__ out_w) {
    __shared__ float4 hv[256];
    int t = threadIdx.x;
    hv[t] = reinterpret_cast<const float4*>(g_h)[t];
    __syncthreads();
    int warp = t >> 5, lane = t & 31;
    int r = blockIdx.x * 8 + warp;
    if (r >= V) return;
    float acc = warp_dot(reinterpret_cast<const float4*>(out_w + (long)r * (2 * H)),
                         hv, lane);
    if (!lane) g_logh[r] = acc;
}

// ================= join: logits ctx-half + combine =================
__global__ void k_logits_ctx(const float* __restrict__ out_w,
                             const float* __restrict__ out_b,
                             float* __restrict__ dout) {
    __shared__ float4 cv[256];
    int t = threadIdx.x;
    cv[t] = reinterpret_cast<const float4*>(g_ctx)[t];
    __syncthreads();
    int warp = t >> 5, lane = t & 31;
    int r = blockIdx.x * 8 + warp;
    if (r >= V) return;
    float acc = warp_dot(reinterpret_cast<const float4*>(out_w + (long)r * (2 * H) + H),
                         cv, lane);
    if (!lane) dout[r] = g_logh[r] + acc + out_b[r];
}

// ---------------- launch: fork/join graph ----------------
extern "C" void kernel_launch(void* const* d_in, const int* in_sizes, int n_in,
                              void* d_out, int out_size) {
    const int* word = (const int*)d_in[0];
    const float* last_hidden = (const float*)d_in[1];
    const float* enc = (const float*)d_in[2];
    const float* emb = (const float*)d_in[3];
    const float* w_ih = (const float*)d_in[4];
    const float* w_hh = (const float*)d_in[5];
    const float* b_ih = (const float*)d_in[6];
    const float* b_hh = (const float*)d_in[7];
    const float* attn_w = (const float*)d_in[8];
    // d_in[9] = attn_b : constant pre-softmax shift -> softmax-invariant, dropped
    const float* out_w = (const float*)d_in[10];
    const float* out_b = (const float*)d_in[11];
    float* dout = (float*)d_out;

    static cudaStream_t sA = nullptr, sB = nullptr;
    static cudaEvent_t eF = nullptr, eA = nullptr, eB = nullptr;
    if (!sA) {
        cudaStreamCreateWithFlags(&sA, cudaStreamNonBlocking);
        cudaStreamCreateWithFlags(&sB, cudaStreamNonBlocking);
        cudaEventCreateWithFlags(&eF, cudaEventDisableTiming);
        cudaEventCreateWithFlags(&eA, cudaEventDisableTiming);
        cudaEventCreateWithFlags(&eB, cudaEventDisableTiming);
    }

    // head (capture stream)
    k_gates_gru<<<NCHAIN, NT>>>(word, last_hidden, emb, w_ih, w_hh, b_ih, b_hh, dout);
    cudaEventRecord(eF, 0);
    cudaStreamWaitEvent(sA, eF, 0);
    cudaStreamWaitEvent(sB, eF, 0);

    // branch B: h-half of logits (206 MB) — the big stream to hide under
    k_logits_h<<<(V + 7) / 8, NT, 0, sB>>>(out_w);
    cudaEventRecord(eB, sB);

    // branch A: attention chain, barrier-free small kernels
    k_vpart<<<64, NT, 0, sA>>>(attn_w);
    k_scores<<<S / 8, NT, 0, sA>>>(enc);
    k_softctx<<<256, NT, 0, sA>>>(enc, dout);
    k_ctxred<<<1, NT, 0, sA>>>();
    cudaEventRecord(eA, sA);

    // join: ctx-half + combine
    cudaStreamWaitEvent(0, eA, 0);
    cudaStreamWaitEvent(0, eB, 0);
    k_logits_ctx<<<(V + 7) / 8, NT>>>(out_w, out_b, dout);
}